// round 2
// baseline (speedup 1.0000x reference)
#include <cuda_runtime.h>

#define N_NODES 20000
#define FDIM    128
#define HDIM    256
#define E_EDGES 262144
#define T_TRIP  393216
#define OUTD    3
#define MBINS   100

#define BM 64
#define BN 128
#define BK 16

// Scratch ping-pong activation buffers (sized for the larger triplet path).
__device__ float g_bufA[(size_t)T_TRIP * HDIM];
__device__ float g_bufB[(size_t)T_TRIP * HDIM];

// ---------------------------------------------------------------------------
// Packed f32x2 helpers (Blackwell FFMA2: 2x scalar FFMA throughput).
// Guarded: falls back to 2x scalar fmaf if the target lacks .f32x2.
// ---------------------------------------------------------------------------
__device__ __forceinline__ unsigned long long fma2(unsigned long long a,
                                                   unsigned long long b,
                                                   unsigned long long c) {
#if defined(__CUDA_ARCH__) && (__CUDA_ARCH__ >= 1000)
    unsigned long long d;
    asm("fma.rn.f32x2 %0, %1, %2, %3;" : "=l"(d) : "l"(a), "l"(b), "l"(c));
    return d;
#else
    float2 fa, fb, fc;
    asm("mov.b64 {%0, %1}, %2;" : "=f"(fa.x), "=f"(fa.y) : "l"(a));
    asm("mov.b64 {%0, %1}, %2;" : "=f"(fb.x), "=f"(fb.y) : "l"(b));
    asm("mov.b64 {%0, %1}, %2;" : "=f"(fc.x), "=f"(fc.y) : "l"(c));
    fc.x = fmaf(fa.x, fb.x, fc.x);
    fc.y = fmaf(fa.y, fb.y, fc.y);
    unsigned long long d;
    asm("mov.b64 %0, {%1, %2};" : "=l"(d) : "f"(fc.x), "f"(fc.y));
    return d;
#endif
}

__device__ __forceinline__ unsigned long long bcast2(float x) {
    unsigned long long d;
    asm("mov.b64 %0, {%1, %1};" : "=l"(d) : "f"(x));
    return d;
}

__device__ __forceinline__ float2 unpack2(unsigned long long p) {
    float2 r;
    asm("mov.b64 {%0, %1}, %2;" : "=f"(r.x), "=f"(r.y) : "l"(p));
    return r;
}

__device__ __forceinline__ float silu_f(float x) {
    return x / (1.0f + __expf(-x));
}

// ---------------------------------------------------------------------------
// Shared GEMM inner tile: Xs[BK][BM] (K-major) x Ws[BK][BN] -> 4x8 per thread
// ---------------------------------------------------------------------------
__device__ __forceinline__ void gemm_tile(const float (*Xs)[BM],
                                          const float (*Ws)[BN],
                                          int ty, int tx,
                                          unsigned long long acc[4][4]) {
#pragma unroll
    for (int k = 0; k < BK; k++) {
        float4 av = *(const float4*)&Xs[k][ty * 4];
        unsigned long long pa0 = bcast2(av.x);
        unsigned long long pa1 = bcast2(av.y);
        unsigned long long pa2 = bcast2(av.z);
        unsigned long long pa3 = bcast2(av.w);
        ulonglong2 b01 = *(const ulonglong2*)&Ws[k][tx * 8];
        ulonglong2 b23 = *(const ulonglong2*)&Ws[k][tx * 8 + 4];

        acc[0][0] = fma2(pa0, b01.x, acc[0][0]);
        acc[0][1] = fma2(pa0, b01.y, acc[0][1]);
        acc[0][2] = fma2(pa0, b23.x, acc[0][2]);
        acc[0][3] = fma2(pa0, b23.y, acc[0][3]);
        acc[1][0] = fma2(pa1, b01.x, acc[1][0]);
        acc[1][1] = fma2(pa1, b01.y, acc[1][1]);
        acc[1][2] = fma2(pa1, b23.x, acc[1][2]);
        acc[1][3] = fma2(pa1, b23.y, acc[1][3]);
        acc[2][0] = fma2(pa2, b01.x, acc[2][0]);
        acc[2][1] = fma2(pa2, b01.y, acc[2][1]);
        acc[2][2] = fma2(pa2, b23.x, acc[2][2]);
        acc[2][3] = fma2(pa2, b23.y, acc[2][3]);
        acc[3][0] = fma2(pa3, b01.x, acc[3][0]);
        acc[3][1] = fma2(pa3, b01.y, acc[3][1]);
        acc[3][2] = fma2(pa3, b23.x, acc[3][2]);
        acc[3][3] = fma2(pa3, b23.y, acc[3][3]);
    }
}

__device__ __forceinline__ void store_tile_silu(float* __restrict__ Y,
                                                int row0, int n0,
                                                int ty, int tx,
                                                unsigned long long acc[4][4]) {
#pragma unroll
    for (int i = 0; i < 4; i++) {
        int row = row0 + ty * 4 + i;
        float v[8];
#pragma unroll
        for (int j = 0; j < 4; j++) {
            float2 p = unpack2(acc[i][j]);
            v[2 * j]     = silu_f(p.x);
            v[2 * j + 1] = silu_f(p.y);
        }
        float4* dst = (float4*)&Y[(size_t)row * HDIM + n0 + tx * 8];
        dst[0] = make_float4(v[0], v[1], v[2], v[3]);
        dst[1] = make_float4(v[4], v[5], v[6], v[7]);
    }
}

// ---------------------------------------------------------------------------
// Layer 0: fused gather + RBF + GEMM + silu.  MODE 0 = edges, 1 = triplets.
// ---------------------------------------------------------------------------
template <int MODE>
__global__ void __launch_bounds__(256, 2) l0_kernel(
    const float* __restrict__ h,
    const int* __restrict__ iA, const int* __restrict__ iB,
    const int* __restrict__ iC,
    const float* __restrict__ rA, const float* __restrict__ rB,
    const float* __restrict__ cosv, const float* __restrict__ sinv,
    const float* __restrict__ mu,
    const float* __restrict__ W,
    float* __restrict__ Y) {
    const int K  = (MODE == 0) ? 356 : 586;
    const int KT = (MODE == 0) ? 23 * BK : 37 * BK;  // padded K

    __shared__ float Xs[BK][BM];
    __shared__ float Ws[BK][BN];
    __shared__ float mu_s[MBINS];

    int t = threadIdx.x;
    int row0 = blockIdx.x * BM;
    int n0   = blockIdx.y * BN;
    if (t < MBINS) mu_s[t] = mu[t];

    int lm = t >> 2;          // X-load role: row within tile
    int lk = (t & 3) * 4;     // X-load role: k group
    int wk = t >> 4;          // W-load role: k row
    int wn = (t & 15) * 8;    // W-load role: n group
    int ty = t >> 4;          // compute role
    int tx = t & 15;

    int row = row0 + lm;
    const float* hA = h + (size_t)iA[row] * FDIM;
    const float* hB = h + (size_t)iB[row] * FDIM;
    const float* hC = (MODE == 1) ? (h + (size_t)iC[row] * FDIM) : h;
    float ra = rA[row];
    float rb = (MODE == 1) ? rB[row] : 0.0f;
    float cv = (MODE == 1) ? cosv[row] : 0.0f;
    float sv = (MODE == 1) ? sinv[row] : 0.0f;

    unsigned long long acc[4][4];
#pragma unroll
    for (int i = 0; i < 4; i++)
#pragma unroll
        for (int j = 0; j < 4; j++) acc[i][j] = 0ull;

    __syncthreads();  // mu_s ready

    for (int k0 = 0; k0 < KT; k0 += BK) {
        // Build virtual X tile
#pragma unroll
        for (int i = 0; i < 4; i++) {
            int k = k0 + lk + i;
            float v;
            if (MODE == 0) {
                if (k < 128)      v = hA[k];
                else if (k < 256) v = hB[k - 128];
                else if (k < 356) { float d = mu_s[k - 256] - ra; v = __expf(-10.0f * d * d); }
                else              v = 0.0f;
            } else {
                if (k < 128)      v = hA[k];
                else if (k < 256) v = hB[k - 128];
                else if (k < 384) v = hC[k - 256];
                else if (k < 484) { float d = mu_s[k - 384] - ra; v = __expf(-10.0f * d * d); }
                else if (k < 584) { float d = mu_s[k - 484] - rb; v = __expf(-10.0f * d * d); }
                else if (k == 584) v = cv;
                else if (k == 585) v = sv;
                else               v = 0.0f;
            }
            Xs[lk + i][lm] = v;
        }
        // Load W tile (zero-pad rows >= K)
        int kw = k0 + wk;
        float4 w0, w1;
        if (kw < K) {
            const float4* wp = (const float4*)(W + (size_t)kw * HDIM + n0 + wn);
            w0 = wp[0];
            w1 = wp[1];
        } else {
            w0 = make_float4(0.f, 0.f, 0.f, 0.f);
            w1 = w0;
        }
        *(float4*)&Ws[wk][wn]     = w0;
        *(float4*)&Ws[wk][wn + 4] = w1;
        __syncthreads();
        gemm_tile(Xs, Ws, ty, tx, acc);
        __syncthreads();
    }
    store_tile_silu(Y, row0, n0, ty, tx, acc);
}

// ---------------------------------------------------------------------------
// Mid layers: Y = silu(X @ W),  X:[rows,256], W:[256,256]
// ---------------------------------------------------------------------------
__global__ void __launch_bounds__(256, 2) mid_kernel(const float* __restrict__ X,
                                                     const float* __restrict__ W,
                                                     float* __restrict__ Y) {
    __shared__ float Xs[BK][BM];
    __shared__ float Ws[BK][BN];

    int t = threadIdx.x;
    int row0 = blockIdx.x * BM;
    int n0   = blockIdx.y * BN;

    int lm = t >> 2, lk = (t & 3) * 4;
    int wk = t >> 4, wn = (t & 15) * 8;
    int ty = t >> 4, tx = t & 15;

    unsigned long long acc[4][4];
#pragma unroll
    for (int i = 0; i < 4; i++)
#pragma unroll
        for (int j = 0; j < 4; j++) acc[i][j] = 0ull;

    const float* xptr = X + (size_t)(row0 + lm) * HDIM + lk;
    const float* wptr = W + (size_t)wk * HDIM + n0 + wn;

    for (int k0 = 0; k0 < HDIM; k0 += BK) {
        float4 xv = *(const float4*)(xptr + k0);
        Xs[lk + 0][lm] = xv.x;
        Xs[lk + 1][lm] = xv.y;
        Xs[lk + 2][lm] = xv.z;
        Xs[lk + 3][lm] = xv.w;
        const float4* wp = (const float4*)(wptr + (size_t)k0 * HDIM);
        float4 w0 = wp[0], w1 = wp[1];
        *(float4*)&Ws[wk][wn]     = w0;
        *(float4*)&Ws[wk][wn + 4] = w1;
        __syncthreads();
        gemm_tile(Xs, Ws, ty, tx, acc);
        __syncthreads();
    }
    store_tile_silu(Y, row0, n0, ty, tx, acc);
}

// ---------------------------------------------------------------------------
// Output layer: out = X @ W3 + b3, W3:[256,3].  One warp per row.
// ---------------------------------------------------------------------------
__global__ void __launch_bounds__(256) out_kernel(const float* __restrict__ X,
                                                  const float* __restrict__ W3,
                                                  const float* __restrict__ b3,
                                                  float* __restrict__ out) {
    __shared__ float Ws[HDIM * OUTD];
    int t = threadIdx.x;
    for (int i = t; i < HDIM * OUTD; i += 256) Ws[i] = W3[i];
    __syncthreads();

    int row  = blockIdx.x * 8 + (t >> 5);
    int lane = t & 31;
    const float* xr = X + (size_t)row * HDIM;
    float s0 = 0.f, s1 = 0.f, s2 = 0.f;
#pragma unroll
    for (int k = lane; k < HDIM; k += 32) {
        float x = xr[k];
        s0 = fmaf(x, Ws[k * 3 + 0], s0);
        s1 = fmaf(x, Ws[k * 3 + 1], s1);
        s2 = fmaf(x, Ws[k * 3 + 2], s2);
    }
#pragma unroll
    for (int o = 16; o; o >>= 1) {
        s0 += __shfl_down_sync(0xffffffffu, s0, o);
        s1 += __shfl_down_sync(0xffffffffu, s1, o);
        s2 += __shfl_down_sync(0xffffffffu, s2, o);
    }
    if (lane == 0) {
        out[(size_t)row * 3 + 0] = s0 + b3[0];
        out[(size_t)row * 3 + 1] = s1 + b3[1];
        out[(size_t)row * 3 + 2] = s2 + b3[2];
    }
}

// ---------------------------------------------------------------------------
extern "C" void kernel_launch(void* const* d_in, const int* in_sizes, int n_in,
                              void* d_out, int out_size) {
    const float* h     = (const float*)d_in[0];
    const int*   src   = (const int*)d_in[1];
    const int*   dst   = (const int*)d_in[2];
    const float* enorm = (const float*)d_in[3];
    const int*   tsrc  = (const int*)d_in[4];
    const int*   tdi   = (const int*)d_in[5];
    const int*   tdj   = (const int*)d_in[6];
    const float* nij   = (const float*)d_in[7];
    const float* nik   = (const float*)d_in[8];
    const float* cosv  = (const float*)d_in[9];
    const float* sinv  = (const float*)d_in[10];
    const float* mu    = (const float*)d_in[11];
    const float* eW0   = (const float*)d_in[12];
    const float* eW1   = (const float*)d_in[13];
    const float* eW2   = (const float*)d_in[14];
    const float* eW3   = (const float*)d_in[15];
    const float* eb3   = (const float*)d_in[16];
    const float* tW0   = (const float*)d_in[17];
    const float* tW1   = (const float*)d_in[18];
    const float* tW2   = (const float*)d_in[19];
    const float* tW3   = (const float*)d_in[20];
    const float* tb3   = (const float*)d_in[21];
    float* out = (float*)d_out;

    float *bufA, *bufB;
    cudaGetSymbolAddress((void**)&bufA, g_bufA);
    cudaGetSymbolAddress((void**)&bufB, g_bufB);

    dim3 g_e(E_EDGES / BM, HDIM / BN);
    dim3 g_t(T_TRIP / BM, HDIM / BN);

    // Edge path
    l0_kernel<0><<<g_e, 256>>>(h, src, dst, nullptr, enorm, nullptr, nullptr,
                               nullptr, mu, eW0, bufA);
    mid_kernel<<<g_e, 256>>>(bufA, eW1, bufB);
    mid_kernel<<<g_e, 256>>>(bufB, eW2, bufA);
    out_kernel<<<E_EDGES / 8, 256>>>(bufA, eW3, eb3, out);

    // Triplet path
    l0_kernel<1><<<g_t, 256>>>(h, tsrc, tdi, tdj, nij, nik, cosv, sinv, mu,
                               tW0, bufA);
    mid_kernel<<<g_t, 256>>>(bufA, tW1, bufB);
    mid_kernel<<<g_t, 256>>>(bufB, tW2, bufA);
    out_kernel<<<T_TRIP / 8, 256>>>(bufA, tW3, tb3, out + (size_t)E_EDGES * 3);
}